// round 17
// baseline (speedup 1.0000x reference)
#include <cuda_runtime.h>
#include <cstdint>

#define B 32
#define T 1024
#define D 384
#define T_OUT 4096
#define F4_PER_ROW (D / 4)        // 96
#define ROWS_PER_THREAD 8
#define ROW_LANES 4               // 384 / 96
#define ROWS_PER_BLOCK (ROW_LANES * ROWS_PER_THREAD)   // 32
#define BLOCKS_PER_BATCH (T_OUT / ROWS_PER_BLOCK)      // 128
#define SCAN_THREADS 256          // each scans 4 contiguous durations (int4)

// dynamic SMEM layout (bytes)
#define SMEM_ENDS_OFF 0                       // (T+1) ints = 4100 B
#define SMEM_WARP_OFF 4104                    // 8 ints
#define SMEM_IDX_OFF  4144                    // 32 ints
#define SMEM_OUT_OFF  4272                    // 16B aligned, 48 KB staging
#define OUT_TILE_BYTES (ROWS_PER_BLOCK * D * 4)   // 49152
#define SMEM_TOTAL (SMEM_OUT_OFF + OUT_TILE_BYTES) // 53424

// ---------------------------------------------------------------------------
// Fused LengthRegulator with TMA bulk stores.
// Hypothesis: the 39.5us invariant across all STG-based variants is the
// L1tex store-wavefront path (shared with gather LDGs), NOT the LTS byte cap
// (L2 counter only 45%). Each block's 32 output rows are contiguous 48 KB ->
// stage in SMEM, then ONE cp.async.bulk store per block, freeing the L1tex
// queue for loads.
// grid = B * BLOCKS_PER_BATCH = 4096, block = 384
// ---------------------------------------------------------------------------
__global__ __launch_bounds__(384) void fused_kernel(
    const float4* __restrict__ x,        // [B, T, 96] as float4
    const int4*   __restrict__ dur4,     // [B, T/4] as int4
    const int*    __restrict__ target_len,
    float4*       __restrict__ out)      // [B, T_OUT, 96] as float4
{
    extern __shared__ char smem_raw[];
    int*    s_ends = (int*)(smem_raw + SMEM_ENDS_OFF);
    int*    s_warp = (int*)(smem_raw + SMEM_WARP_OFF);
    int*    s_idx  = (int*)(smem_raw + SMEM_IDX_OFF);
    float4* s_out  = (float4*)(smem_raw + SMEM_OUT_OFF);

    const int tid   = threadIdx.x;
    const int b     = blockIdx.x / BLOCKS_PER_BATCH;
    const int chunk = blockIdx.x - b * BLOCKS_PER_BATCH;

    // ---- 1) block-local scan of this batch's durations (first 256 threads)
    if (tid < SCAN_THREADS) {
        const int lane = tid & 31;
        const int wid  = tid >> 5;

        int4 d = __ldg(&dur4[b * (T / 4) + tid]);
        int e0 = d.x < 0 ? 0 : d.x;
        int e1 = d.y < 0 ? 0 : d.y;
        int e2 = d.z < 0 ? 0 : d.z;
        int e3 = d.w < 0 ? 0 : d.w;
        int p0 = e0, p1 = p0 + e1, p2 = p1 + e2, p3 = p2 + e3;

        // warp inclusive scan of per-thread sums (p3)
        int ws = p3;
        #pragma unroll
        for (int off = 1; off < 32; off <<= 1) {
            int n = __shfl_up_sync(0xFFFFFFFFu, ws, off);
            if (lane >= off) ws += n;
        }
        if (lane == 31) s_warp[wid] = ws;
        __syncthreads();

        if (wid == 0 && lane < 8) {
            int w = s_warp[lane];
            #pragma unroll
            for (int off = 1; off < 8; off <<= 1) {
                int n = __shfl_up_sync(0xFFu, w, off);
                if (lane >= off) w += n;
            }
            s_warp[lane] = w;
        }
        __syncthreads();

        const int warp_off = (wid > 0) ? s_warp[wid - 1] : 0;
        const int base = warp_off + (ws - p3);
        s_ends[4 * tid + 0] = base + p0;
        s_ends[4 * tid + 1] = base + p1;
        s_ends[4 * tid + 2] = base + p2;
        s_ends[4 * tid + 3] = base + p3;
        if (tid == 0) s_ends[T] = 0x7FFFFFFF;    // sentinel
    } else {
        __syncthreads();
        __syncthreads();
    }
    __syncthreads();

    // ---- 2) searchsorted for this block's 32 output positions
    if (tid < ROWS_PER_BLOCK) {
        const int pos   = chunk * ROWS_PER_BLOCK + tid;
        const int total = s_ends[T - 1];
        const int tl    = __ldg(&target_len[b]);
        const int limit = total < tl ? total : tl;

        int lo = 0, hi = T;
        #pragma unroll
        for (int it = 0; it < 11; it++) {   // answer space {0..T} -> 11 iters
            int mid = (lo + hi) >> 1;
            if (s_ends[mid] <= pos) lo = mid + 1; else hi = mid;
        }
        int idx = lo < (T - 1) ? lo : (T - 1);
        s_idx[tid] = (pos < limit) ? idx : -1;
    }
    __syncthreads();

    // ---- 3) gather into SMEM staging tile (STS instead of STG)
    const int rsub = tid / F4_PER_ROW;           // 0..3
    const int c    = tid - rsub * F4_PER_ROW;    // 0..95

    #pragma unroll
    for (int k = 0; k < ROWS_PER_THREAD; k++) {
        const int r   = rsub + k * ROW_LANES;
        const int idx = s_idx[r];
        float4 val;
        if (idx >= 0) {
            val = __ldg(&x[((long)b * T + idx) * F4_PER_ROW + c]);
        } else {
            val = make_float4(0.f, 0.f, 0.f, 0.f);
        }
        s_out[r * F4_PER_ROW + c] = val;
    }
    __syncthreads();

    // ---- 4) one TMA bulk store: SMEM tile -> contiguous 48 KB of out
    if (tid == 0) {
        const long row_base = (long)b * T_OUT + chunk * ROWS_PER_BLOCK;
        void* dst = (void*)((char*)out + row_base * (D * 4));
        uint32_t src_smem;
        asm("{ .reg .u64 t; cvta.to.shared.u64 t, %1; cvt.u32.u64 %0, t; }"
            : "=r"(src_smem) : "l"((void*)s_out));
        // order generic-proxy STS before async-proxy bulk read
        asm volatile("fence.proxy.async.shared::cta;" ::: "memory");
        asm volatile(
            "cp.async.bulk.global.shared::cta.bulk_group [%0], [%1], %2;"
            :: "l"(dst), "r"(src_smem), "r"((int)OUT_TILE_BYTES) : "memory");
        asm volatile("cp.async.bulk.commit_group;" ::: "memory");
        // SMEM must stay alive until the bulk read completes
        asm volatile("cp.async.bulk.wait_group.read 0;" ::: "memory");
    }
}

// ---------------------------------------------------------------------------
extern "C" void kernel_launch(void* const* d_in, const int* in_sizes, int n_in,
                              void* d_out, int out_size)
{
    const float* x          = (const float*)d_in[0];
    const int*   durations  = (const int*)d_in[1];
    const int*   target_len = (const int*)d_in[2];
    float*       out        = (float*)d_out;

    // >48KB dynamic smem opt-in (idempotent, host-side, capture-safe)
    cudaFuncSetAttribute(fused_kernel,
                         cudaFuncAttributeMaxDynamicSharedMemorySize, SMEM_TOTAL);

    fused_kernel<<<B * BLOCKS_PER_BATCH, 384, SMEM_TOTAL>>>(
        (const float4*)x, (const int4*)durations, target_len, (float4*)out);
}